// round 1
// baseline (speedup 1.0000x reference)
#include <cuda_runtime.h>
#include <math.h>

// Problem constants (fixed shapes)
#define BB 2
#define LL 2048
#define DD 1024
#define HH 16
#define DK 64
#define NBH (BB*HH)            // 32
#define NROWS (NBH*LL)         // 65536
#define TOPK 1024

// Scratch (device globals; no dynamic allocation allowed)
__device__ float g_Q  [BB*HH*LL*DK];          // [b,h,l,d] 16MB
__device__ float g_K  [BB*HH*LL*DK];          // [b,h,l,d] 16MB
__device__ float g_Vt [BB*HH*DK*LL];          // [b,h,d,l] 16MB (transposed for NT gemm)
__device__ float g_S  [134217728];            // [bh, q, k] 512MB (scores -> probs in place)
__device__ float g_ctx[BB*LL*DD];             // [b,l,D] 16MB

// ---------------------------------------------------------------------------
// Generic NT GEMM: C = scale * A[M,K] * W[N,K]^T + bias
// MODE 0: C[z*sC + m*N + n]                  (plain, batched)
// MODE 1: head-major out   [b,h,l,d]         (Q/K projections)
// MODE 2: head-transposed  [b,h,d,l]         (V projection)
// MODE 3: ctx out          [b, l(=m), h*64+n] (attn @ V, batched over bh)
// ---------------------------------------------------------------------------
template<int MODE>
__global__ __launch_bounds__(256)
void gemm_nt(const float* __restrict__ A, const float* __restrict__ W,
             const float* __restrict__ bias, float* __restrict__ C,
             int M, int N, int K,
             long long sA, long long sW, long long sC, float scale)
{
    __shared__ float As[16][68];
    __shared__ float Bs[16][68];

    const int z = blockIdx.z;
    const float* Ab = A + (long long)z * sA;
    const float* Wb = W + (long long)z * sW;
    const int m0 = blockIdx.y * 64;
    const int n0 = blockIdx.x * 64;
    const int tid = threadIdx.x;
    const int tx = tid & 15, ty = tid >> 4;
    const int mm = tid >> 2;           // 0..63
    const int kq = (tid & 3) << 2;     // 0,4,8,12

    float acc[4][4];
#pragma unroll
    for (int i = 0; i < 4; i++)
#pragma unroll
        for (int j = 0; j < 4; j++) acc[i][j] = 0.f;

    for (int k0 = 0; k0 < K; k0 += 16) {
        float4 a4 = *reinterpret_cast<const float4*>(Ab + (long long)(m0 + mm) * K + k0 + kq);
        float4 w4 = *reinterpret_cast<const float4*>(Wb + (long long)(n0 + mm) * K + k0 + kq);
        As[kq + 0][mm] = a4.x; As[kq + 1][mm] = a4.y; As[kq + 2][mm] = a4.z; As[kq + 3][mm] = a4.w;
        Bs[kq + 0][mm] = w4.x; Bs[kq + 1][mm] = w4.y; Bs[kq + 2][mm] = w4.z; Bs[kq + 3][mm] = w4.w;
        __syncthreads();
#pragma unroll
        for (int kk = 0; kk < 16; kk++) {
            float4 a = *reinterpret_cast<const float4*>(&As[kk][ty << 2]);
            float4 b = *reinterpret_cast<const float4*>(&Bs[kk][tx << 2]);
            float av[4] = {a.x, a.y, a.z, a.w};
            float bv[4] = {b.x, b.y, b.z, b.w};
#pragma unroll
            for (int i = 0; i < 4; i++)
#pragma unroll
                for (int j = 0; j < 4; j++) acc[i][j] += av[i] * bv[j];
        }
        __syncthreads();
    }

#pragma unroll
    for (int i = 0; i < 4; i++) {
        const int m = m0 + (ty << 2) + i;
#pragma unroll
        for (int j = 0; j < 4; j++) {
            const int n = n0 + (tx << 2) + j;
            float v = acc[i][j] * scale + (bias ? bias[n] : 0.f);
            if (MODE == 0) {
                C[(long long)z * sC + (long long)m * N + n] = v;
            } else if (MODE == 1) {
                // m = b*2048 + l ; n = h*64 + d  ->  [b,h,l,d]
                C[((((m >> 11) * 16 + (n >> 6)) * 2048) + (m & 2047)) * 64 + (n & 63)] = v;
            } else if (MODE == 2) {
                // -> [b,h,d,l]
                C[((((m >> 11) * 16 + (n >> 6)) * 64) + (n & 63)) * 2048 + (m & 2047)] = v;
            } else { // MODE 3: z = b*16+h, m = q, n = d -> ctx[b, q, h*64+d]
                C[((long long)(((z >> 4) * 2048) + m)) * 1024 + (z & 15) * 64 + n] = v;
            }
        }
    }
}

// ---------------------------------------------------------------------------
// Per-row exact top-1024 selection + softmax, in place: scores -> probs
// One block (256 thr) per row of 2048 scores.
// ---------------------------------------------------------------------------
__device__ __forceinline__ unsigned f2key(float f) {
    unsigned u = __float_as_uint(f);
    return (u & 0x80000000u) ? ~u : (u | 0x80000000u);  // monotonic: bigger float -> bigger key
}

__global__ __launch_bounds__(256)
void topk_softmax_kernel(float* __restrict__ S)
{
    __shared__ float s[LL];          // 8KB: row of scores
    __shared__ int   hist[256];
    __shared__ float redF[256];
    __shared__ int   redI[256];
    __shared__ unsigned sh_prefix;
    __shared__ int   sh_k, s_run, s_cut, s_neq;
    __shared__ int   warpCnt[8];

    const long long row = blockIdx.x;
    float* Srow = S + row * LL;
    const int tid = threadIdx.x;

    float lmax = -INFINITY;
#pragma unroll
    for (int i = 0; i < 8; i++) {
        float v = Srow[tid + i * 256];
        s[tid + i * 256] = v;
        lmax = fmaxf(lmax, v);
    }
    if (tid == 0) { sh_prefix = 0u; sh_k = TOPK; s_run = 0; s_cut = -1; }
    __syncthreads();

    // ---- radix select (4 x 8-bit passes, descending) for the TOPK-th key ----
    for (int pass = 3; pass >= 0; pass--) {
        hist[tid] = 0;
        __syncthreads();
        const unsigned pref  = sh_prefix;
        const unsigned hmask = (pass == 3) ? 0u : (0xFFFFFFFFu << ((pass + 1) * 8));
#pragma unroll
        for (int i = 0; i < 8; i++) {
            unsigned key = f2key(s[tid + i * 256]);
            if ((key & hmask) == (pref & hmask))
                atomicAdd(&hist[(key >> (pass * 8)) & 255], 1);
        }
        __syncthreads();
        if (tid == 0) {
            int kk = sh_k, cum = 0, b = 255;
            for (; b >= 0; b--) { cum += hist[b]; if (cum >= kk) break; }
            sh_k = kk - (cum - hist[b]);
            sh_prefix = pref | ((unsigned)b << (pass * 8));
        }
        __syncthreads();
    }
    const unsigned tkey = sh_prefix;   // key of the 1024-th largest value

    // ---- count strictly-greater + row max ----
    int cgt = 0;
#pragma unroll
    for (int i = 0; i < 8; i++)
        if (f2key(s[tid + i * 256]) > tkey) cgt++;
    redI[tid] = cgt; redF[tid] = lmax;
    __syncthreads();
    for (int st = 128; st > 0; st >>= 1) {
        if (tid < st) {
            redI[tid] += redI[tid + st];
            redF[tid] = fmaxf(redF[tid], redF[tid + st]);
        }
        __syncthreads();
    }
    if (tid == 0) s_neq = TOPK - redI[0];
    const float m = redF[0];
    __syncthreads();
    const int n_eq = s_neq;   // >= 1 always

    // ---- index-ordered tie cutoff (matches lax.top_k lowest-index-first) ----
    const int lane = tid & 31, warp = tid >> 5;
    for (int base = 0; base < LL; base += 256) {
        const int idx = base + tid;
        const bool eq = (f2key(s[idx]) == tkey);
        const unsigned ball = __ballot_sync(0xffffffffu, eq);
        if (lane == 0) warpCnt[warp] = __popc(ball);
        __syncthreads();
        int wpre = 0;
        for (int w = 0; w < warp; w++) wpre += warpCnt[w];
        const int pos = s_run + wpre + __popc(ball & ((1u << lane) - 1u));
        if (eq && pos < n_eq) atomicMax(&s_cut, idx);
        __syncthreads();
        if (tid == 0) { int tot = 0; for (int w = 0; w < 8; w++) tot += warpCnt[w]; s_run += tot; }
        __syncthreads();
    }
    const int cut = s_cut;

    // ---- Z over included set ----
    float lz = 0.f;
#pragma unroll
    for (int i = 0; i < 8; i++) {
        const int idx = tid + i * 256;
        const float v = s[idx];
        const unsigned key = f2key(v);
        const bool inc = (key > tkey) || (key == tkey && idx <= cut);
        if (inc) lz += expf(v - m);
    }
    redF[tid] = lz;
    __syncthreads();
    for (int st = 128; st > 0; st >>= 1) {
        if (tid < st) redF[tid] += redF[tid + st];
        __syncthreads();
    }
    const float invZ = 1.0f / redF[0];

    // ---- write probabilities in place ----
#pragma unroll
    for (int i = 0; i < 8; i++) {
        const int idx = tid + i * 256;
        const float v = s[idx];
        const unsigned key = f2key(v);
        const bool inc = (key > tkey) || (key == tkey && idx <= cut);
        Srow[idx] = inc ? expf(v - m) * invZ : 0.f;
    }
}

// ---------------------------------------------------------------------------
extern "C" void kernel_launch(void* const* d_in, const int* in_sizes, int n_in,
                              void* d_out, int out_size)
{
    const float* q  = (const float*)d_in[0];
    const float* k  = (const float*)d_in[1];
    const float* v  = (const float*)d_in[2];
    const float* Wq = (const float*)d_in[3];
    const float* bq = (const float*)d_in[4];
    const float* Wk = (const float*)d_in[5];
    const float* bk = (const float*)d_in[6];
    const float* Wv = (const float*)d_in[7];
    const float* bv = (const float*)d_in[8];
    const float* Wo = (const float*)d_in[9];
    const float* bo = (const float*)d_in[10];
    float* out = (float*)d_out;

    float *Qd, *Kd, *Vtd, *Sd, *Cd;
    cudaGetSymbolAddress((void**)&Qd,  g_Q);
    cudaGetSymbolAddress((void**)&Kd,  g_K);
    cudaGetSymbolAddress((void**)&Vtd, g_Vt);
    cudaGetSymbolAddress((void**)&Sd,  g_S);
    cudaGetSymbolAddress((void**)&Cd,  g_ctx);

    const dim3 blk(256);

    // Projections: [4096,1024] x [1024,1024]^T
    gemm_nt<1><<<dim3(DD / 64, (BB * LL) / 64, 1), blk>>>(q, Wq, bq, Qd,  BB * LL, DD, DD, 0, 0, 0, 1.f);
    gemm_nt<1><<<dim3(DD / 64, (BB * LL) / 64, 1), blk>>>(k, Wk, bk, Kd,  BB * LL, DD, DD, 0, 0, 0, 1.f);
    gemm_nt<2><<<dim3(DD / 64, (BB * LL) / 64, 1), blk>>>(v, Wv, bv, Vtd, BB * LL, DD, DD, 0, 0, 0, 1.f);

    // Scores: per (b,h): [2048,64] x [2048,64]^T, scale 1/8
    gemm_nt<0><<<dim3(LL / 64, LL / 64, NBH), blk>>>(
        Qd, Kd, nullptr, Sd, LL, LL, DK,
        (long long)LL * DK, (long long)LL * DK, (long long)LL * LL, 0.125f);

    // Exact top-1024 + softmax, in place (scores -> probs)
    topk_softmax_kernel<<<NROWS, 256>>>(Sd);

    // ctx = P @ V : per (b,h): [2048,2048] x [64,2048]^T -> ctx[b,l,D]
    gemm_nt<3><<<dim3(DK / 64, LL / 64, NBH), blk>>>(
        Sd, Vtd, nullptr, Cd, LL, DK, LL,
        (long long)LL * LL, (long long)DK * LL, 0, 1.f);

    // Output projection: [4096,1024] x [1024,1024]^T + bo
    gemm_nt<0><<<dim3(DD / 64, (BB * LL) / 64, 1), blk>>>(Cd, Wo, bo, out, BB * LL, DD, DD, 0, 0, 0, 1.f);
}

// round 2
// speedup vs baseline: 1.0627x; 1.0627x over previous
#include <cuda_runtime.h>
#include <math.h>

// Problem constants (fixed shapes)
#define BB 2
#define LL 2048
#define DD 1024
#define HH 16
#define DK 64
#define NBH (BB*HH)            // 32
#define NROWS (NBH*LL)         // 65536
#define TOPK 1024

// Scratch (device globals; no dynamic allocation allowed)
__device__ float g_Q  [BB*HH*LL*DK];          // [b,h,l,d] 16MB
__device__ float g_K  [BB*HH*LL*DK];          // [b,h,l,d] 16MB
__device__ float g_Vt [BB*HH*DK*LL];          // [b,h,d,l] 16MB (transposed for NT gemm)
__device__ float g_S  [134217728];            // [bh, q, k] 512MB (scores -> probs in place)
__device__ float g_ctx[BB*LL*DD];             // [b,l,D] 16MB

// ---------------------------------------------------------------------------
// NT GEMM: C = scale * A[M,K] * W[N,K]^T + bias
// 8x8 microtile, BMxBN block, BK=16 k-tile, double-buffered shared memory.
// MODE 0: C[z*sC + m*N + n]                  (plain, batched)
// MODE 1: head-major out   [b,h,l,d]         (Q/K projections)
// MODE 2: head-transposed  [b,h,d,l]         (V projection)
// MODE 3: ctx out          [b, l(=m), h*64+n] (attn @ V, batched over bh)
// ---------------------------------------------------------------------------
template<int BM, int BN, int BK, int MODE>
__global__ __launch_bounds__((BM/8)*(BN/8))
void gemm_nt(const float* __restrict__ A, const float* __restrict__ W,
             const float* __restrict__ bias, float* __restrict__ C,
             int M, int N, int K,
             long long sA, long long sW, long long sC, float scale)
{
    constexpr int TX  = BN / 8;
    constexpr int TY  = BM / 8;
    constexpr int NTH = TX * TY;
    constexpr int KQ  = BK / 4;               // float4 per row of a tile
    constexpr int LA  = BM * KQ / NTH;        // float4 loads per thread (A tile)
    constexpr int LB  = BN * KQ / NTH;        // float4 loads per thread (B tile)

    __shared__ float As[2][BK][BM + 4];
    __shared__ float Bs[2][BK][BN + 4];

    const int z  = blockIdx.z;
    const float* Ab = A + (long long)z * sA;
    const float* Wb = W + (long long)z * sW;
    const int m0 = blockIdx.y * BM;
    const int n0 = blockIdx.x * BN;
    const int tid = threadIdx.x;
    const int tx = tid % TX;
    const int ty = tid / TX;

    float4 ra[LA], rb[LB];

    auto loadA = [&](int k0) {
#pragma unroll
        for (int i = 0; i < LA; i++) {
            int f = tid + i * NTH;
            int r = f / KQ, c = (f % KQ) * 4;
            ra[i] = *reinterpret_cast<const float4*>(Ab + (long long)(m0 + r) * K + k0 + c);
        }
    };
    auto loadB = [&](int k0) {
#pragma unroll
        for (int i = 0; i < LB; i++) {
            int f = tid + i * NTH;
            int r = f / KQ, c = (f % KQ) * 4;
            rb[i] = *reinterpret_cast<const float4*>(Wb + (long long)(n0 + r) * K + k0 + c);
        }
    };
    auto storeA = [&](int buf) {
#pragma unroll
        for (int i = 0; i < LA; i++) {
            int f = tid + i * NTH;
            int r = f / KQ, c = (f % KQ) * 4;
            As[buf][c + 0][r] = ra[i].x; As[buf][c + 1][r] = ra[i].y;
            As[buf][c + 2][r] = ra[i].z; As[buf][c + 3][r] = ra[i].w;
        }
    };
    auto storeB = [&](int buf) {
#pragma unroll
        for (int i = 0; i < LB; i++) {
            int f = tid + i * NTH;
            int r = f / KQ, c = (f % KQ) * 4;
            Bs[buf][c + 0][r] = rb[i].x; Bs[buf][c + 1][r] = rb[i].y;
            Bs[buf][c + 2][r] = rb[i].z; Bs[buf][c + 3][r] = rb[i].w;
        }
    };

    float acc[8][8];
#pragma unroll
    for (int i = 0; i < 8; i++)
#pragma unroll
        for (int j = 0; j < 8; j++) acc[i][j] = 0.f;

    loadA(0); loadB(0); storeA(0); storeB(0);
    __syncthreads();

    int buf = 0;
    for (int k0 = 0; k0 < K; k0 += BK) {
        const bool pref = (k0 + BK) < K;
        if (pref) { loadA(k0 + BK); loadB(k0 + BK); }
#pragma unroll
        for (int kk = 0; kk < BK; kk++) {
            float4 a0 = *reinterpret_cast<const float4*>(&As[buf][kk][ty * 8]);
            float4 a1 = *reinterpret_cast<const float4*>(&As[buf][kk][ty * 8 + 4]);
            float4 b0 = *reinterpret_cast<const float4*>(&Bs[buf][kk][tx * 8]);
            float4 b1 = *reinterpret_cast<const float4*>(&Bs[buf][kk][tx * 8 + 4]);
            float av[8] = {a0.x, a0.y, a0.z, a0.w, a1.x, a1.y, a1.z, a1.w};
            float bv[8] = {b0.x, b0.y, b0.z, b0.w, b1.x, b1.y, b1.z, b1.w};
#pragma unroll
            for (int i = 0; i < 8; i++)
#pragma unroll
                for (int j = 0; j < 8; j++) acc[i][j] += av[i] * bv[j];
        }
        if (pref) { storeA(buf ^ 1); storeB(buf ^ 1); __syncthreads(); buf ^= 1; }
    }

    // ---- epilogue ----
    if (MODE == 2) {
        // [b,h,d,l]: contiguous along m (=l) -> vectorize over i
#pragma unroll
        for (int j = 0; j < 8; j++) {
            const int n = n0 + tx * 8 + j;
            const float bsum = bias ? bias[n] : 0.f;
#pragma unroll
            for (int ig = 0; ig < 2; ig++) {
                const int m = m0 + ty * 8 + ig * 4;
                float4 vv;
                vv.x = acc[ig * 4 + 0][j] * scale + bsum;
                vv.y = acc[ig * 4 + 1][j] * scale + bsum;
                vv.z = acc[ig * 4 + 2][j] * scale + bsum;
                vv.w = acc[ig * 4 + 3][j] * scale + bsum;
                long long idx = ((((long long)(m >> 11) * 16 + (n >> 6)) * 64) + (n & 63)) * 2048 + (m & 2047);
                *reinterpret_cast<float4*>(&C[idx]) = vv;
            }
        }
    } else {
#pragma unroll
        for (int i = 0; i < 8; i++) {
            const int m = m0 + ty * 8 + i;
#pragma unroll
            for (int jg = 0; jg < 2; jg++) {
                const int n = n0 + tx * 8 + jg * 4;
                float4 vv;
                vv.x = acc[i][jg * 4 + 0] * scale + (bias ? bias[n + 0] : 0.f);
                vv.y = acc[i][jg * 4 + 1] * scale + (bias ? bias[n + 1] : 0.f);
                vv.z = acc[i][jg * 4 + 2] * scale + (bias ? bias[n + 2] : 0.f);
                vv.w = acc[i][jg * 4 + 3] * scale + (bias ? bias[n + 3] : 0.f);
                long long idx;
                if (MODE == 0) {
                    idx = (long long)z * sC + (long long)m * N + n;
                } else if (MODE == 1) {
                    idx = (((long long)(m >> 11) * 16 + (n >> 6)) * 2048 + (m & 2047)) * 64 + (n & 63);
                } else { // MODE 3
                    idx = ((long long)((z >> 4) * 2048 + m)) * 1024 + (z & 15) * 64 + n;
                }
                *reinterpret_cast<float4*>(&C[idx]) = vv;
            }
        }
    }
}

// ---------------------------------------------------------------------------
// Per-row exact top-1024 selection + softmax, in place: scores -> probs
// One block (256 thr) per row of 2048 scores.
// ---------------------------------------------------------------------------
__device__ __forceinline__ unsigned f2key(float f) {
    unsigned u = __float_as_uint(f);
    return (u & 0x80000000u) ? ~u : (u | 0x80000000u);  // monotonic: bigger float -> bigger key
}

__global__ __launch_bounds__(256)
void topk_softmax_kernel(float* __restrict__ S)
{
    __shared__ float s[LL];          // 8KB: row of scores
    __shared__ int   hist[256];
    __shared__ float redF[256];
    __shared__ int   redI[256];
    __shared__ int   redE[256];
    __shared__ unsigned sh_prefix;
    __shared__ int   sh_k, s_run, s_cut;
    __shared__ int   warpCnt[8];

    const long long row = blockIdx.x;
    float* Srow = S + row * LL;
    const int tid = threadIdx.x;

    float lmax = -INFINITY;
#pragma unroll
    for (int i = 0; i < 8; i++) {
        float v = Srow[tid + i * 256];
        s[tid + i * 256] = v;
        lmax = fmaxf(lmax, v);
    }
    if (tid == 0) { sh_prefix = 0u; sh_k = TOPK; s_run = 0; s_cut = -1; }
    __syncthreads();

    // ---- radix select (4 x 8-bit passes, descending) for the TOPK-th key ----
    for (int pass = 3; pass >= 0; pass--) {
        hist[tid] = 0;
        __syncthreads();
        const unsigned pref  = sh_prefix;
        const unsigned hmask = (pass == 3) ? 0u : (0xFFFFFFFFu << ((pass + 1) * 8));
#pragma unroll
        for (int i = 0; i < 8; i++) {
            unsigned key = f2key(s[tid + i * 256]);
            if ((key & hmask) == (pref & hmask))
                atomicAdd(&hist[(key >> (pass * 8)) & 255], 1);
        }
        __syncthreads();
        if (tid == 0) {
            int kk = sh_k, cum = 0, b = 255;
            for (; b >= 0; b--) { cum += hist[b]; if (cum >= kk) break; }
            sh_k = kk - (cum - hist[b]);
            sh_prefix = pref | ((unsigned)b << (pass * 8));
        }
        __syncthreads();
    }
    const unsigned tkey = sh_prefix;   // key of the 1024-th largest value

    // ---- count strictly-greater, count equal, row max (one fused reduction) ----
    int cgt = 0, ceq = 0;
#pragma unroll
    for (int i = 0; i < 8; i++) {
        unsigned key = f2key(s[tid + i * 256]);
        if (key > tkey) cgt++;
        else if (key == tkey) ceq++;
    }
    redI[tid] = cgt; redE[tid] = ceq; redF[tid] = lmax;
    __syncthreads();
    for (int st = 128; st > 0; st >>= 1) {
        if (tid < st) {
            redI[tid] += redI[tid + st];
            redE[tid] += redE[tid + st];
            redF[tid] = fmaxf(redF[tid], redF[tid + st]);
        }
        __syncthreads();
    }
    const int n_eq    = TOPK - redI[0];  // how many "equal" elements are included
    const int tot_eq  = redE[0];
    const float m     = redF[0];
    __syncthreads();

    int cut;
    if (n_eq >= tot_eq) {
        // fast path (virtually always): every tied element is included
        cut = LL - 1;
    } else {
        // slow path: index-ordered tie cutoff (matches lax.top_k lowest-index-first)
        const int lane = tid & 31, warp = tid >> 5;
        for (int base = 0; base < LL; base += 256) {
            const int idx = base + tid;
            const bool eq = (f2key(s[idx]) == tkey);
            const unsigned ball = __ballot_sync(0xffffffffu, eq);
            if (lane == 0) warpCnt[warp] = __popc(ball);
            __syncthreads();
            int wpre = 0;
            for (int w = 0; w < warp; w++) wpre += warpCnt[w];
            const int pos = s_run + wpre + __popc(ball & ((1u << lane) - 1u));
            if (eq && pos < n_eq) atomicMax(&s_cut, idx);
            __syncthreads();
            if (tid == 0) { int tot = 0; for (int w = 0; w < 8; w++) tot += warpCnt[w]; s_run += tot; }
            __syncthreads();
        }
        cut = s_cut;
    }

    // ---- Z over included set ----
    float lz = 0.f;
#pragma unroll
    for (int i = 0; i < 8; i++) {
        const int idx = tid + i * 256;
        const float v = s[idx];
        const unsigned key = f2key(v);
        const bool inc = (key > tkey) || (key == tkey && idx <= cut);
        if (inc) lz += __expf(v - m);
    }
    redF[tid] = lz;
    __syncthreads();
    for (int st = 128; st > 0; st >>= 1) {
        if (tid < st) redF[tid] += redF[tid + st];
        __syncthreads();
    }
    const float invZ = 1.0f / redF[0];

    // ---- write probabilities in place ----
#pragma unroll
    for (int i = 0; i < 8; i++) {
        const int idx = tid + i * 256;
        const float v = s[idx];
        const unsigned key = f2key(v);
        const bool inc = (key > tkey) || (key == tkey && idx <= cut);
        Srow[idx] = inc ? __expf(v - m) * invZ : 0.f;
    }
}

// ---------------------------------------------------------------------------
extern "C" void kernel_launch(void* const* d_in, const int* in_sizes, int n_in,
                              void* d_out, int out_size)
{
    const float* q  = (const float*)d_in[0];
    const float* k  = (const float*)d_in[1];
    const float* v  = (const float*)d_in[2];
    const float* Wq = (const float*)d_in[3];
    const float* bq = (const float*)d_in[4];
    const float* Wk = (const float*)d_in[5];
    const float* bk = (const float*)d_in[6];
    const float* Wv = (const float*)d_in[7];
    const float* bv = (const float*)d_in[8];
    const float* Wo = (const float*)d_in[9];
    const float* bo = (const float*)d_in[10];
    float* out = (float*)d_out;

    float *Qd, *Kd, *Vtd, *Sd, *Cd;
    cudaGetSymbolAddress((void**)&Qd,  g_Q);
    cudaGetSymbolAddress((void**)&Kd,  g_K);
    cudaGetSymbolAddress((void**)&Vtd, g_Vt);
    cudaGetSymbolAddress((void**)&Sd,  g_S);
    cudaGetSymbolAddress((void**)&Cd,  g_ctx);

    // Projections: [4096,1024] x [1024,1024]^T  (128x128 tiles, 256 thr)
    gemm_nt<128,128,16,1><<<dim3(DD/128, (BB*LL)/128, 1), 256>>>(q, Wq, bq, Qd,  BB*LL, DD, DD, 0, 0, 0, 1.f);
    gemm_nt<128,128,16,1><<<dim3(DD/128, (BB*LL)/128, 1), 256>>>(k, Wk, bk, Kd,  BB*LL, DD, DD, 0, 0, 0, 1.f);
    gemm_nt<128,128,16,2><<<dim3(DD/128, (BB*LL)/128, 1), 256>>>(v, Wv, bv, Vtd, BB*LL, DD, DD, 0, 0, 0, 1.f);

    // Scores: per (b,h): [2048,64] x [2048,64]^T, scale 1/8
    gemm_nt<128,128,16,0><<<dim3(LL/128, LL/128, NBH), 256>>>(
        Qd, Kd, nullptr, Sd, LL, LL, DK,
        (long long)LL*DK, (long long)LL*DK, (long long)LL*LL, 0.125f);

    // Exact top-1024 + softmax, in place (scores -> probs)
    topk_softmax_kernel<<<NROWS, 256>>>(Sd);

    // ctx = P @ V : per (b,h): [2048,2048] x [64,2048]^T -> ctx[b,l,D]  (128x64 tiles, 128 thr)
    gemm_nt<128,64,16,3><<<dim3(DK/64, LL/128, NBH), 128>>>(
        Sd, Vtd, nullptr, Cd, LL, DK, LL,
        (long long)LL*LL, (long long)DK*LL, 0, 1.f);

    // Output projection: [4096,1024] x [1024,1024]^T + bo
    gemm_nt<128,128,16,0><<<dim3(DD/128, (BB*LL)/128, 1), 256>>>(Cd, Wo, bo, out, BB*LL, DD, DD, 0, 0, 0, 1.f);
}

// round 5
// speedup vs baseline: 1.1871x; 1.1170x over previous
#include <cuda_runtime.h>
#include <math.h>
#include <stdint.h>

// Problem constants (fixed shapes)
#define BB 2
#define LL 2048
#define DD 1024
#define HH 16
#define DK 64
#define NBH (BB*HH)            // 32
#define NROWS (NBH*LL)         // 65536
#define TOPK 1024

// Scratch (device globals; no dynamic allocation allowed)
__device__ float g_Qf [BB*HH*LL*DK];   // [b,h,l,d] fp32 16MB
__device__ float g_Kf [BB*HH*LL*DK];   // [b,h,l,d] fp32 16MB
__device__ float g_Vt [BB*HH*DK*LL];   // [b,h,d,l] fp32 16MB
__device__ float g_ctx[BB*LL*DD];      // [b,l,D]   fp32 16MB
__device__ float g_S  [134217728];     // [bh,q,k]  512MB (scores -> probs in place)

// ---------------------------------------------------------------------------
// FFMA fp32 NT GEMM (selection-critical path; numerics identical to round 2)
// 8x8 microtile, BMxBN block, BK=16, double-buffered smem.
// MODE 0: C[z*sC + m*N + n]   MODE 1: head-major [b,h,l,64]
// ---------------------------------------------------------------------------
template<int BM, int BN, int BK, int MODE>
__global__ __launch_bounds__((BM/8)*(BN/8))
void gemm_nt(const float* __restrict__ A, const float* __restrict__ W,
             const float* __restrict__ bias, float* __restrict__ C,
             int M, int N, int K,
             long long sA, long long sW, long long sC, float scale)
{
    constexpr int TX  = BN / 8;
    constexpr int TY  = BM / 8;
    constexpr int NTH = TX * TY;
    constexpr int KQ  = BK / 4;
    constexpr int LA  = BM * KQ / NTH;
    constexpr int LB  = BN * KQ / NTH;

    __shared__ float As[2][BK][BM + 4];
    __shared__ float Bs[2][BK][BN + 4];

    const int z = blockIdx.z;
    const float* Ab = A + (long long)z * sA;
    const float* Wb = W + (long long)z * sW;
    const int m0 = blockIdx.y * BM;
    const int n0 = blockIdx.x * BN;
    const int tid = threadIdx.x;
    const int tx = tid % TX;
    const int ty = tid / TX;

    float4 ra[LA], rb[LB];

    auto loadA = [&](int k0) {
#pragma unroll
        for (int i = 0; i < LA; i++) {
            int f = tid + i * NTH;
            int r = f / KQ, c = (f % KQ) * 4;
            ra[i] = *reinterpret_cast<const float4*>(Ab + (long long)(m0 + r) * K + k0 + c);
        }
    };
    auto loadB = [&](int k0) {
#pragma unroll
        for (int i = 0; i < LB; i++) {
            int f = tid + i * NTH;
            int r = f / KQ, c = (f % KQ) * 4;
            rb[i] = *reinterpret_cast<const float4*>(Wb + (long long)(n0 + r) * K + k0 + c);
        }
    };
    auto storeA = [&](int buf) {
#pragma unroll
        for (int i = 0; i < LA; i++) {
            int f = tid + i * NTH;
            int r = f / KQ, c = (f % KQ) * 4;
            As[buf][c + 0][r] = ra[i].x; As[buf][c + 1][r] = ra[i].y;
            As[buf][c + 2][r] = ra[i].z; As[buf][c + 3][r] = ra[i].w;
        }
    };
    auto storeB = [&](int buf) {
#pragma unroll
        for (int i = 0; i < LB; i++) {
            int f = tid + i * NTH;
            int r = f / KQ, c = (f % KQ) * 4;
            Bs[buf][c + 0][r] = rb[i].x; Bs[buf][c + 1][r] = rb[i].y;
            Bs[buf][c + 2][r] = rb[i].z; Bs[buf][c + 3][r] = rb[i].w;
        }
    };

    float acc[8][8];
#pragma unroll
    for (int i = 0; i < 8; i++)
#pragma unroll
        for (int j = 0; j < 8; j++) acc[i][j] = 0.f;

    loadA(0); loadB(0); storeA(0); storeB(0);
    __syncthreads();

    int buf = 0;
    for (int k0 = 0; k0 < K; k0 += BK) {
        const bool pref = (k0 + BK) < K;
        if (pref) { loadA(k0 + BK); loadB(k0 + BK); }
#pragma unroll
        for (int kk = 0; kk < BK; kk++) {
            float4 a0 = *reinterpret_cast<const float4*>(&As[buf][kk][ty * 8]);
            float4 a1 = *reinterpret_cast<const float4*>(&As[buf][kk][ty * 8 + 4]);
            float4 b0 = *reinterpret_cast<const float4*>(&Bs[buf][kk][tx * 8]);
            float4 b1 = *reinterpret_cast<const float4*>(&Bs[buf][kk][tx * 8 + 4]);
            float av[8] = {a0.x, a0.y, a0.z, a0.w, a1.x, a1.y, a1.z, a1.w};
            float bv[8] = {b0.x, b0.y, b0.z, b0.w, b1.x, b1.y, b1.z, b1.w};
#pragma unroll
            for (int i = 0; i < 8; i++)
#pragma unroll
                for (int j = 0; j < 8; j++) acc[i][j] += av[i] * bv[j];
        }
        if (pref) { storeA(buf ^ 1); storeB(buf ^ 1); __syncthreads(); buf ^= 1; }
    }

#pragma unroll
    for (int i = 0; i < 8; i++) {
        const int m = m0 + ty * 8 + i;
#pragma unroll
        for (int jg = 0; jg < 2; jg++) {
            const int n = n0 + tx * 8 + jg * 4;
            float4 vv;
            vv.x = acc[i][jg * 4 + 0] * scale + (bias ? bias[n + 0] : 0.f);
            vv.y = acc[i][jg * 4 + 1] * scale + (bias ? bias[n + 1] : 0.f);
            vv.z = acc[i][jg * 4 + 2] * scale + (bias ? bias[n + 2] : 0.f);
            vv.w = acc[i][jg * 4 + 3] * scale + (bias ? bias[n + 3] : 0.f);
            long long idx;
            if (MODE == 0) {
                idx = (long long)z * sC + (long long)m * N + n;
            } else {
                idx = (((long long)(m >> 11) * 16 + (n >> 6)) * 2048 + (m & 2047)) * 64 + (n & 63);
            }
            *reinterpret_cast<float4*>(&C[idx]) = vv;
        }
    }
}

// ---------------------------------------------------------------------------
// Split-tf32 NT GEMM (value-only path, ~7e-7 rel): C = scale*A*B^T + bias
// 3 passes: hi*hi + hi*lo + lo*hi.
// OMODE 0: fp32 plain [z*sC + m*ldc + n]
// OMODE 2: fp32 head-transposed [b,h,d,l]
// OMODE 3: fp32 ctx [b,l,h*64+d], z = b*16+h
// ---------------------------------------------------------------------------
__device__ __forceinline__ void mma_tf32(float (&c)[4], const uint32_t (&a)[4], const uint32_t (&b)[2]) {
    asm volatile("mma.sync.aligned.m16n8k8.row.col.f32.tf32.tf32.f32 "
                 "{%0,%1,%2,%3},{%4,%5,%6,%7},{%8,%9},{%0,%1,%2,%3};"
                 : "+f"(c[0]), "+f"(c[1]), "+f"(c[2]), "+f"(c[3])
                 : "r"(a[0]), "r"(a[1]), "r"(a[2]), "r"(a[3]), "r"(b[0]), "r"(b[1]));
}
__device__ __forceinline__ uint32_t f2tf32(float x) {
    uint32_t r; asm("cvt.rna.tf32.f32 %0,%1;" : "=r"(r) : "f"(x)); return r;
}
__device__ __forceinline__ void split_tf32(float x, uint32_t& hi, uint32_t& lo) {
    hi = f2tf32(x);
    lo = f2tf32(x - __uint_as_float(hi));
}

template<int BM, int BN, int BK, int WM, int WN, int OMODE>
__global__ __launch_bounds__(256)
void gemm_tf32(const float* __restrict__ A, const float* __restrict__ B,
               const float* __restrict__ bias, float* __restrict__ C,
               int K, int lda, int ldb, int ldc,
               long long sAb, long long sBb, long long sCb, float scale)
{
    constexpr int SKP = BK + 4;
    constexpr int WNB = BN / WN;
    constexpr int MT = WM / 16, NT = WN / 8;
    constexpr int LA = BM * (BK / 4) / 256, LB = BN * (BK / 4) / 256;

    __shared__ __align__(16) float sA[BM * SKP];
    __shared__ __align__(16) float sB[BN * SKP];

    const int z   = blockIdx.z;
    const float* Ab = A + (long long)z * sAb;
    const float* Bb = B + (long long)z * sBb;
    const int m0  = blockIdx.y * BM, n0 = blockIdx.x * BN;
    const int tid = threadIdx.x, lane = tid & 31, warp = tid >> 5;
    const int wm0 = (warp / WNB) * WM, wn0 = (warp % WNB) * WN;

    float4 ra[LA], rb[LB];
    auto loadA = [&](int k0) {
#pragma unroll
        for (int i = 0; i < LA; i++) {
            int f = tid + i * 256, r = f / (BK / 4), c = (f % (BK / 4)) * 4;
            ra[i] = *reinterpret_cast<const float4*>(Ab + (size_t)(m0 + r) * lda + k0 + c);
        }
    };
    auto loadB = [&](int k0) {
#pragma unroll
        for (int i = 0; i < LB; i++) {
            int f = tid + i * 256, r = f / (BK / 4), c = (f % (BK / 4)) * 4;
            rb[i] = *reinterpret_cast<const float4*>(Bb + (size_t)(n0 + r) * ldb + k0 + c);
        }
    };
    auto storeA = [&]() {
#pragma unroll
        for (int i = 0; i < LA; i++) {
            int f = tid + i * 256, r = f / (BK / 4), c = (f % (BK / 4)) * 4;
            sA[r * SKP + c + 0] = ra[i].x; sA[r * SKP + c + 1] = ra[i].y;
            sA[r * SKP + c + 2] = ra[i].z; sA[r * SKP + c + 3] = ra[i].w;
        }
    };
    auto storeB = [&]() {
#pragma unroll
        for (int i = 0; i < LB; i++) {
            int f = tid + i * 256, r = f / (BK / 4), c = (f % (BK / 4)) * 4;
            sB[r * SKP + c + 0] = rb[i].x; sB[r * SKP + c + 1] = rb[i].y;
            sB[r * SKP + c + 2] = rb[i].z; sB[r * SKP + c + 3] = rb[i].w;
        }
    };

    float acc[MT][NT][4];
#pragma unroll
    for (int i = 0; i < MT; i++)
#pragma unroll
        for (int j = 0; j < NT; j++)
#pragma unroll
            for (int t = 0; t < 4; t++) acc[i][j][t] = 0.f;

    loadA(0); loadB(0);

    for (int k0 = 0; k0 < K; k0 += BK) {
        storeA(); storeB();
        __syncthreads();
        if (k0 + BK < K) { loadA(k0 + BK); loadB(k0 + BK); }

#pragma unroll
        for (int kk = 0; kk < BK; kk += 8) {
            uint32_t bh[NT][2], bl[NT][2];
#pragma unroll
            for (int nt = 0; nt < NT; nt++) {
                int n  = wn0 + nt * 8 + (lane >> 2);
                int kc = kk + (lane & 3);
                split_tf32(sB[n * SKP + kc],     bh[nt][0], bl[nt][0]);
                split_tf32(sB[n * SKP + kc + 4], bh[nt][1], bl[nt][1]);
            }
#pragma unroll
            for (int mt = 0; mt < MT; mt++) {
                uint32_t ah[4], al[4];
                int r0 = wm0 + mt * 16 + (lane >> 2);
                int kc = kk + (lane & 3);
                split_tf32(sA[r0 * SKP + kc],           ah[0], al[0]);
                split_tf32(sA[(r0 + 8) * SKP + kc],     ah[1], al[1]);
                split_tf32(sA[r0 * SKP + kc + 4],       ah[2], al[2]);
                split_tf32(sA[(r0 + 8) * SKP + kc + 4], ah[3], al[3]);
#pragma unroll
                for (int nt = 0; nt < NT; nt++) {
                    mma_tf32(acc[mt][nt], ah, bh[nt]);
                    mma_tf32(acc[mt][nt], ah, bl[nt]);
                    mma_tf32(acc[mt][nt], al, bh[nt]);
                }
            }
        }
        __syncthreads();
    }

#pragma unroll
    for (int mt = 0; mt < MT; mt++)
#pragma unroll
        for (int nt = 0; nt < NT; nt++)
#pragma unroll
            for (int h2 = 0; h2 < 2; h2++) {
                int row = m0 + wm0 + mt * 16 + (lane >> 2) + h2 * 8;
                int col = n0 + wn0 + nt * 8 + ((lane & 3) << 1);
                float v0 = acc[mt][nt][h2 * 2 + 0] * scale;
                float v1 = acc[mt][nt][h2 * 2 + 1] * scale;
                if (bias) { v0 += bias[col]; v1 += bias[col + 1]; }
                if constexpr (OMODE == 0) {
                    float2 vv = {v0, v1};
                    *reinterpret_cast<float2*>(C + (long long)z * sCb + (size_t)row * ldc + col) = vv;
                } else if constexpr (OMODE == 2) {
                    // [b,h,d,l]: col = h*64+d, row = b*2048+l
                    size_t idx = ((((size_t)(row >> 11) * 16 + (col >> 6)) * 64) + (col & 63)) * 2048 + (row & 2047);
                    C[idx] = v0;
                    C[idx + 2048] = v1;
                } else { // OMODE 3: ctx [b, l, h*64+d]
                    size_t idx = (((size_t)(z >> 4) * 2048 + row) * 1024) + (size_t)(z & 15) * 64 + col;
                    float2 vv = {v0, v1};
                    *reinterpret_cast<float2*>(C + idx) = vv;
                }
            }
}

// ---------------------------------------------------------------------------
// Per-row exact top-1024 selection + softmax, in place: scores -> probs
// ---------------------------------------------------------------------------
__device__ __forceinline__ unsigned f2key(float f) {
    unsigned u = __float_as_uint(f);
    return (u & 0x80000000u) ? ~u : (u | 0x80000000u);
}

__global__ __launch_bounds__(256)
void topk_softmax_kernel(float* __restrict__ S)
{
    __shared__ float s[LL];
    __shared__ int   hist[256];
    __shared__ float redF[256];
    __shared__ int   redI[256];
    __shared__ int   redE[256];
    __shared__ unsigned sh_prefix;
    __shared__ int   sh_k, s_run, s_cut;
    __shared__ int   warpCnt[8];

    const long long row = blockIdx.x;
    float* Srow = S + row * LL;
    const int tid = threadIdx.x;

    float lmax = -INFINITY;
#pragma unroll
    for (int i = 0; i < 8; i++) {
        float v = Srow[tid + i * 256];
        s[tid + i * 256] = v;
        lmax = fmaxf(lmax, v);
    }
    if (tid == 0) { sh_prefix = 0u; sh_k = TOPK; s_run = 0; s_cut = -1; }
    __syncthreads();

    for (int pass = 3; pass >= 0; pass--) {
        hist[tid] = 0;
        __syncthreads();
        const unsigned pref  = sh_prefix;
        const unsigned hmask = (pass == 3) ? 0u : (0xFFFFFFFFu << ((pass + 1) * 8));
#pragma unroll
        for (int i = 0; i < 8; i++) {
            unsigned key = f2key(s[tid + i * 256]);
            if ((key & hmask) == (pref & hmask))
                atomicAdd(&hist[(key >> (pass * 8)) & 255], 1);
        }
        __syncthreads();
        if (tid == 0) {
            int kk = sh_k, cum = 0, b = 255;
            for (; b >= 0; b--) { cum += hist[b]; if (cum >= kk) break; }
            sh_k = kk - (cum - hist[b]);
            sh_prefix = pref | ((unsigned)b << (pass * 8));
        }
        __syncthreads();
    }
    const unsigned tkey = sh_prefix;

    int cgt = 0, ceq = 0;
#pragma unroll
    for (int i = 0; i < 8; i++) {
        unsigned key = f2key(s[tid + i * 256]);
        if (key > tkey) cgt++;
        else if (key == tkey) ceq++;
    }
    redI[tid] = cgt; redE[tid] = ceq; redF[tid] = lmax;
    __syncthreads();
    for (int st = 128; st > 0; st >>= 1) {
        if (tid < st) {
            redI[tid] += redI[tid + st];
            redE[tid] += redE[tid + st];
            redF[tid] = fmaxf(redF[tid], redF[tid + st]);
        }
        __syncthreads();
    }
    const int n_eq   = TOPK - redI[0];
    const int tot_eq = redE[0];
    const float m    = redF[0];
    __syncthreads();

    int cut;
    if (n_eq >= tot_eq) {
        cut = LL - 1;
    } else {
        const int lane = tid & 31, warp = tid >> 5;
        for (int base = 0; base < LL; base += 256) {
            const int idx = base + tid;
            const bool eq = (f2key(s[idx]) == tkey);
            const unsigned ball = __ballot_sync(0xffffffffu, eq);
            if (lane == 0) warpCnt[warp] = __popc(ball);
            __syncthreads();
            int wpre = 0;
            for (int w = 0; w < warp; w++) wpre += warpCnt[w];
            const int pos = s_run + wpre + __popc(ball & ((1u << lane) - 1u));
            if (eq && pos < n_eq) atomicMax(&s_cut, idx);
            __syncthreads();
            if (tid == 0) { int tot = 0; for (int w = 0; w < 8; w++) tot += warpCnt[w]; s_run += tot; }
            __syncthreads();
        }
        cut = s_cut;
    }

    float lz = 0.f;
#pragma unroll
    for (int i = 0; i < 8; i++) {
        const int idx = tid + i * 256;
        const float v = s[idx];
        const unsigned key = f2key(v);
        const bool inc = (key > tkey) || (key == tkey && idx <= cut);
        if (inc) lz += __expf(v - m);
    }
    redF[tid] = lz;
    __syncthreads();
    for (int st = 128; st > 0; st >>= 1) {
        if (tid < st) redF[tid] += redF[tid + st];
        __syncthreads();
    }
    const float invZ = 1.0f / redF[0];

#pragma unroll
    for (int i = 0; i < 8; i++) {
        const int idx = tid + i * 256;
        const float v = s[idx];
        const unsigned key = f2key(v);
        const bool inc = (key > tkey) || (key == tkey && idx <= cut);
        Srow[idx] = inc ? __expf(v - m) * invZ : 0.f;
    }
}

// ---------------------------------------------------------------------------
extern "C" void kernel_launch(void* const* d_in, const int* in_sizes, int n_in,
                              void* d_out, int out_size)
{
    const float* q  = (const float*)d_in[0];
    const float* k  = (const float*)d_in[1];
    const float* v  = (const float*)d_in[2];
    const float* Wq = (const float*)d_in[3];
    const float* bq = (const float*)d_in[4];
    const float* Wk = (const float*)d_in[5];
    const float* bk = (const float*)d_in[6];
    const float* Wv = (const float*)d_in[7];
    const float* bv = (const float*)d_in[8];
    const float* Wo = (const float*)d_in[9];
    const float* bo = (const float*)d_in[10];
    float* out = (float*)d_out;

    float *Qf, *Kf, *Vt, *Cd, *Sd;
    cudaGetSymbolAddress((void**)&Qf, g_Qf);
    cudaGetSymbolAddress((void**)&Kf, g_Kf);
    cudaGetSymbolAddress((void**)&Vt, g_Vt);
    cudaGetSymbolAddress((void**)&Cd, g_ctx);
    cudaGetSymbolAddress((void**)&Sd, g_S);

    // --- Selection-critical chain: fp32 FFMA (numerics identical to round 2) ---
    // Q/K projections -> fp32 head-major [b,h,l,64]   (128x64 tiles, 128 thr)
    gemm_nt<128,64,16,1><<<dim3(DD/64, (BB*LL)/128, 1), 128>>>(
        q, Wq, bq, Qf, BB*LL, DD, DD, 0, 0, 0, 1.f);
    gemm_nt<128,64,16,1><<<dim3(DD/64, (BB*LL)/128, 1), 128>>>(
        k, Wk, bk, Kf, BB*LL, DD, DD, 0, 0, 0, 1.f);

    // Scores: per (b,h) [2048,64] x [2048,64]^T, scale 1/8 -> fp32 S
    gemm_nt<128,64,16,0><<<dim3(LL/64, LL/128, NBH), 128>>>(
        Qf, Kf, nullptr, Sd, LL, LL, DK,
        (long long)LL*DK, (long long)LL*DK, (long long)LL*LL, 0.125f);

    // Exact top-1024 + softmax, in place (scores -> probs)
    topk_softmax_kernel<<<NROWS, 256>>>(Sd);

    // --- Value-only chain: split-tf32 tensor cores (~7e-7 rel) ---
    // V projection -> fp32 head-transposed Vt [b,h,d,l]
    gemm_tf32<128,128,16,64,32,2><<<dim3(8,32,1),256>>>(
        v, Wv, bv, Vt, DD, DD, DD, 0, 0, 0, 0, 1.f);

    // ctx = P @ Vt^T : per (b,h) [2048,2048] x [64,2048]^T -> ctx [b,l,D]
    gemm_tf32<128,64,16,32,32,3><<<dim3(1,16,NBH),256>>>(
        Sd, Vt, nullptr, Cd, LL, LL, LL, 0,
        (long long)LL*LL, (long long)DK*LL, 0, 1.f);

    // Output projection: ctx x Wo^T + bo -> out
    gemm_tf32<128,128,16,64,32,0><<<dim3(8,32,1),256>>>(
        Cd, Wo, bo, out, DD, DD, DD, DD, 0, 0, 0, 1.f);
}